// round 1
// baseline (speedup 1.0000x reference)
#include <cuda_runtime.h>
#include <cstddef>

typedef unsigned long long u64;

#define NB 128
#define NS 64
#define NH 32
#define ND 128
#define KPAD 132   // K row stride in floats: 132*4B = 528B -> conflict-free column reads

// ---- packed f32x2 helpers (Blackwell FFMA2 path) ----
__device__ __forceinline__ u64 fma2(u64 a, u64 b, u64 c) {
    u64 d; asm("fma.rn.f32x2 %0, %1, %2, %3;" : "=l"(d) : "l"(a), "l"(b), "l"(c)); return d;
}
__device__ __forceinline__ u64 dup2(float x) {
    u64 d; asm("mov.b64 %0, {%1, %1};" : "=l"(d) : "f"(x), "f"(x)); return d;
}
__device__ __forceinline__ float2 unpk(u64 v) {
    float2 r; asm("mov.b64 {%0, %1}, %2;" : "=f"(r.x), "=f"(r.y) : "l"(v)); return r;
}

// SMEM layout (floats): Q[64][128] | K[64][132] | V[64][128]
// P (softmax probs, duplicated f32x2) reuses the warp's own dead Q rows.
#define SM_Q 0
#define SM_K (NS*ND)
#define SM_V (SM_K + NS*KPAD)
#define SMEM_FLOATS (SM_V + NS*ND)
#define SMEM_BYTES (SMEM_FLOATS * 4)

__global__ __launch_bounds__(256, 2)
void attn_kernel(const float* __restrict__ qkv, const int* __restrict__ kvp,
                 float* __restrict__ out)
{
    extern __shared__ float sm[];
    float* Qs = sm + SM_Q;
    float* Ks = sm + SM_K;
    float* Vs = sm + SM_V;

    const int h    = blockIdx.x & (NH - 1);
    const int b    = blockIdx.x >> 5;
    const int tid  = threadIdx.x;
    const int w    = tid >> 5;
    const int lane = tid & 31;
    const int kvlen = kvp ? *kvp : NS;

    // ---- load phase: coalesced float4 (each warp loads rows w, w+8, ...) ----
    const float* base = qkv + ((size_t)b * NS * NH + h) * (3 * ND);
    for (int r = w; r < NS; r += 8) {
        const float4* src = (const float4*)(base + (size_t)r * (NH * 3 * ND));
        ((float4*)(Qs + r * ND))[lane]   = src[lane];        // Q: d in [0,128)
        ((float4*)(Ks + r * KPAD))[lane] = src[32 + lane];   // K: d in [128,256)
        ((float4*)(Vs + r * ND))[lane]   = src[64 + lane];   // V: d in [256,384)
    }
    __syncthreads();

    const int r0 = w * 8;   // this warp's 8 query rows

    // ---- phase A: scores. acc[r][j] packed (even-d, odd-d) partial sums ----
    u64 acc[8][2];
    #pragma unroll
    for (int r = 0; r < 8; r++) { acc[r][0] = 0ull; acc[r][1] = 0ull; }

    const ulonglong2* k0p = (const ulonglong2*)(Ks + lane * KPAD);          // key = lane
    const ulonglong2* k1p = (const ulonglong2*)(Ks + (lane + 32) * KPAD);   // key = lane+32
    #pragma unroll 4
    for (int d4 = 0; d4 < ND / 4; d4++) {
        ulonglong2 k0 = k0p[d4];
        ulonglong2 k1 = k1p[d4];
        #pragma unroll
        for (int r = 0; r < 8; r++) {
            ulonglong2 q = ((const ulonglong2*)(Qs + (r0 + r) * ND))[d4];  // broadcast
            acc[r][0] = fma2(q.x, k0.x, acc[r][0]);
            acc[r][0] = fma2(q.y, k0.y, acc[r][0]);
            acc[r][1] = fma2(q.x, k1.x, acc[r][1]);
            acc[r][1] = fma2(q.y, k1.y, acc[r][1]);
        }
    }

    // ---- phase B: softmax per row; write duplicated probs into dead Q rows ----
    __syncwarp();   // all lanes done reading this warp's Q rows
    u64* Pw64 = (u64*)(Qs + r0 * ND);   // 512 u64 = 4KB, exactly the warp's Q slice
    const float scale = 0.08838834764831843f;  // 1/sqrt(128)

    #pragma unroll
    for (int r = 0; r < 8; r++) {
        float2 a0 = unpk(acc[r][0]);
        float2 a1 = unpk(acc[r][1]);
        float s0 = (a0.x + a0.y) * scale;
        float s1 = (a1.x + a1.y) * scale;
        if (lane >= kvlen)      s0 = -1e30f;
        if (lane + 32 >= kvlen) s1 = -1e30f;
        float m = fmaxf(s0, s1);
        #pragma unroll
        for (int o = 16; o; o >>= 1) m = fmaxf(m, __shfl_xor_sync(0xffffffffu, m, o));
        float e0 = __expf(s0 - m);
        float e1 = __expf(s1 - m);
        float ss = e0 + e1;
        #pragma unroll
        for (int o = 16; o; o >>= 1) ss += __shfl_xor_sync(0xffffffffu, ss, o);
        float inv = 1.0f / ss;
        // layout: Pw64[k*8 + r], each entry = (p, p) for mov-free f32x2 FMAs
        Pw64[lane * 8 + r]        = dup2(e0 * inv);
        Pw64[(lane + 32) * 8 + r] = dup2(e1 * inv);
    }
    __syncwarp();

    // ---- phase C: O = P @ V. Each lane owns dims [lane*4, lane*4+4). ----
    u64 o[8][2];
    #pragma unroll
    for (int r = 0; r < 8; r++) { o[r][0] = 0ull; o[r][1] = 0ull; }

    #pragma unroll 2
    for (int k = 0; k < NS; k++) {
        ulonglong2 v = ((const ulonglong2*)(Vs + k * ND))[lane];   // 4 V dims
        const ulonglong2* pk = (const ulonglong2*)(Pw64 + k * 8);  // broadcast
        ulonglong2 p01 = pk[0], p23 = pk[1], p45 = pk[2], p67 = pk[3];
        o[0][0] = fma2(p01.x, v.x, o[0][0]);  o[0][1] = fma2(p01.x, v.y, o[0][1]);
        o[1][0] = fma2(p01.y, v.x, o[1][0]);  o[1][1] = fma2(p01.y, v.y, o[1][1]);
        o[2][0] = fma2(p23.x, v.x, o[2][0]);  o[2][1] = fma2(p23.x, v.y, o[2][1]);
        o[3][0] = fma2(p23.y, v.x, o[3][0]);  o[3][1] = fma2(p23.y, v.y, o[3][1]);
        o[4][0] = fma2(p45.x, v.x, o[4][0]);  o[4][1] = fma2(p45.x, v.y, o[4][1]);
        o[5][0] = fma2(p45.y, v.x, o[5][0]);  o[5][1] = fma2(p45.y, v.y, o[5][1]);
        o[6][0] = fma2(p67.x, v.x, o[6][0]);  o[6][1] = fma2(p67.x, v.y, o[6][1]);
        o[7][0] = fma2(p67.y, v.x, o[7][0]);  o[7][1] = fma2(p67.y, v.y, o[7][1]);
    }

    // ---- store: coalesced 128B per warp-row ----
    #pragma unroll
    for (int r = 0; r < 8; r++) {
        ulonglong2 res; res.x = o[r][0]; res.y = o[r][1];
        *(((ulonglong2*)(out + ((size_t)(b * NS + r0 + r) * NH + h) * ND)) + lane) = res;
    }
}

extern "C" void kernel_launch(void* const* d_in, const int* in_sizes, int n_in,
                              void* d_out, int out_size)
{
    const float* qkv  = (const float*)d_in[0];
    const int*   kvlp = (n_in > 1) ? (const int*)d_in[1] : nullptr;
    float*       out  = (float*)d_out;

    cudaFuncSetAttribute(attn_kernel, cudaFuncAttributeMaxDynamicSharedMemorySize, SMEM_BYTES);
    attn_kernel<<<NB * NH, 256, SMEM_BYTES>>>(qkv, kvlp, out);
}